// round 8
// baseline (speedup 1.0000x reference)
#include <cuda_runtime.h>

#define N_NODES 100000
#define N_EDGES 200000
#define IN_DIM  384
#define HID     128

// ---------------- device scratch (no allocations allowed) ----------------
// PR holds [P | R] = [h@Wl | h@Wr] as one [N, 256] row-major matrix.
// Reused across both layers (layer 1 fully consumes it before layer 2 writes).
__device__ float g_PR [(size_t)N_NODES * 256];   // 102.4 MB
__device__ float g_h  [(size_t)N_NODES * HID];   //  51.2 MB
__device__ float g_agg[(size_t)N_NODES * HID];   //  51.2 MB
__device__ int   g_cnt[N_NODES];

__device__ __forceinline__ int clampN(int v) {
    return v < 0 ? 0 : (v >= N_NODES ? N_NODES - 1 : v);
}

// =====================================================================
// GEMM: C[N_NODES, 256] = A[N_NODES, K] @ [Wl | Wr]  (Wl, Wr are [K,128])
// blockIdx.y selects the Wl half (cols 0..127) or Wr half (cols 128..255).
// BM=128, BN=128, BK=8, 256 threads, 8x8 outputs/thread. Plain FFMA.
// =====================================================================
template<int K, bool L2>
__global__ __launch_bounds__(256, 2) void gemm_dual(
    const float* __restrict__ Aext,
    const float* __restrict__ Wl,
    const float* __restrict__ Wr)
{
    constexpr int BM = 128, BN = 128, BK = 8;
    __shared__ __align__(16) float As[BK][BM];   // transposed A tile, 4 KB
    __shared__ __align__(16) float Bs[BK][BN];   // 4 KB

    const float* __restrict__ A = L2 ? g_h : Aext;

    const int m0     = blockIdx.x * BM;
    const float* __restrict__ W = blockIdx.y ? Wr : Wl;
    const int colOff = blockIdx.y * 128;

    const int tid = threadIdx.x;
    const int tx  = tid & 15;     // n-direction (8 cols each)
    const int ty  = tid >> 4;     // m-direction (8 rows each)

    float acc[8][8];
#pragma unroll
    for (int i = 0; i < 8; i++)
#pragma unroll
        for (int j = 0; j < 8; j++) acc[i][j] = 0.f;

    const int arow = tid >> 1;          // 0..127
    const int acol = (tid & 1) << 2;    // 0 or 4
    const int brow = tid >> 5;          // 0..7
    const int bcol = (tid & 31) << 2;   // 0..124

    for (int k0 = 0; k0 < K; k0 += BK) {
        // ---- load A tile (128 x 8), store transposed ----
        {
            int gm = m0 + arow;
            float4 v = make_float4(0.f, 0.f, 0.f, 0.f);
            if (gm < N_NODES)
                v = *(const float4*)(A + (size_t)gm * K + (k0 + acol));
            As[acol + 0][arow] = v.x;
            As[acol + 1][arow] = v.y;
            As[acol + 2][arow] = v.z;
            As[acol + 3][arow] = v.w;
        }
        // ---- load B tile (8 x 128) ----
        *(float4*)&Bs[brow][bcol] =
            *(const float4*)(W + (size_t)(k0 + brow) * HID + bcol);
        __syncthreads();

        // ---- compute ----
#pragma unroll
        for (int kk = 0; kk < BK; kk++) {
            float a[8], b[8];
#pragma unroll
            for (int i = 0; i < 8; i += 4)
                *(float4*)&a[i] = *(const float4*)&As[kk][ty * 8 + i];
#pragma unroll
            for (int j = 0; j < 8; j += 4)
                *(float4*)&b[j] = *(const float4*)&Bs[kk][tx * 8 + j];
#pragma unroll
            for (int i = 0; i < 8; i++)
#pragma unroll
                for (int j = 0; j < 8; j++)
                    acc[i][j] = fmaf(a[i], b[j], acc[i][j]);
        }
        __syncthreads();
    }

    // ---- epilogue ----
#pragma unroll
    for (int i = 0; i < 8; i++) {
        int gm = m0 + ty * 8 + i;
        if (gm < N_NODES) {
            float* c = g_PR + (size_t)gm * 256 + colOff + tx * 8;
            *(float4*)(c + 0) = *(const float4*)&acc[i][0];
            *(float4*)(c + 4) = *(const float4*)&acc[i][4];
        }
    }
}

// =====================================================================
// Helper kernels  (edge_index is int32 per harness dtype contract:
// float32/int32/bfloat16 only — int64 inputs are materialized as int32)
// =====================================================================
__global__ void zero_kernel() {
    int idx = blockIdx.x * blockDim.x + threadIdx.x;
    if (idx < N_NODES * (HID / 4))
        ((float4*)g_agg)[idx] = make_float4(0.f, 0.f, 0.f, 0.f);
    if (idx < N_NODES) g_cnt[idx] = 0;
}

__global__ void count_kernel(const int* __restrict__ ei) {
    int e = blockIdx.x * blockDim.x + threadIdx.x;
    if (e < N_EDGES) atomicAdd(&g_cnt[clampN(ei[N_EDGES + e])], 1);
}

// agg[dst] += P[src]  (P part = first 128 cols of PR, row stride 256)
__global__ void scatter_kernel(const int* __restrict__ ei) {
    int idx = blockIdx.x * blockDim.x + threadIdx.x;
    if (idx >= N_EDGES * 32) return;
    int e = idx >> 5, q = idx & 31;
    int src = clampN(ei[e]);
    int dst = clampN(ei[N_EDGES + e]);
    float4 v = *(const float4*)(g_PR + (size_t)src * 256 + q * 4);
    float* d = g_agg + (size_t)dst * HID + q * 4;
    atomicAdd(d + 0, v.x);
    atomicAdd(d + 1, v.y);
    atomicAdd(d + 2, v.z);
    atomicAdd(d + 3, v.w);
}

// out = [relu](agg/max(cnt,1) + bias + R), R = cols 128..255 of PR.
// Layer-1 variant (L2=false) also resets agg to 0 for reuse by layer 2.
template<bool L2>
__global__ void combine_kernel(const float* __restrict__ bias,
                               float* __restrict__ outp) {
    int idx = blockIdx.x * blockDim.x + threadIdx.x;
    if (idx >= N_NODES * 32) return;
    float* __restrict__ o = L2 ? outp : g_h;
    int n = idx >> 5, q = idx & 31;
    int c = g_cnt[n];
    float inv = 1.0f / (float)(c > 0 ? c : 1);
    float4 s  = ((const float4*)g_agg)[idx];
    float4 r  = *(const float4*)(g_PR + (size_t)n * 256 + 128 + q * 4);
    float4 bb = *(const float4*)(bias + q * 4);
    float4 v;
    v.x = fmaf(s.x, inv, bb.x + r.x);
    v.y = fmaf(s.y, inv, bb.y + r.y);
    v.z = fmaf(s.z, inv, bb.z + r.z);
    v.w = fmaf(s.w, inv, bb.w + r.w);
    if (!L2) {
        v.x = fmaxf(v.x, 0.f); v.y = fmaxf(v.y, 0.f);
        v.z = fmaxf(v.z, 0.f); v.w = fmaxf(v.w, 0.f);
        ((float4*)g_agg)[idx] = make_float4(0.f, 0.f, 0.f, 0.f);
    }
    ((float4*)o)[idx] = v;
}

// =====================================================================
extern "C" void kernel_launch(void* const* d_in, const int* in_sizes, int n_in,
                              void* d_out, int out_size) {
    const float* x   = (const float*)d_in[0];
    const int*   ei  = (const int*)d_in[1];      // int64 in ref -> int32 here
    const float* W1l = (const float*)d_in[2];
    const float* b1  = (const float*)d_in[3];
    const float* W1r = (const float*)d_in[4];
    const float* W2l = (const float*)d_in[5];
    const float* b2  = (const float*)d_in[6];
    const float* W2r = (const float*)d_in[7];
    float* out = (float*)d_out;

    const int T = 256;
    const int gM = (N_NODES + 127) / 128;          // 782
    const int gZero    = (N_NODES * 32 + T - 1) / T;
    const int gCount   = (N_EDGES + T - 1) / T;
    const int gScatter = (N_EDGES * 32 + T - 1) / T;

    zero_kernel<<<gZero, T>>>();
    count_kernel<<<gCount, T>>>(ei);

    // Layer 1: PR = x @ [W1l | W1r]
    gemm_dual<IN_DIM, false><<<dim3(gM, 2), T>>>(x, W1l, W1r);
    scatter_kernel<<<gScatter, T>>>(ei);
    combine_kernel<false><<<gZero, T>>>(b1, nullptr);   // -> g_h (relu, agg reset)

    // Layer 2: PR = h @ [W2l | W2r]
    gemm_dual<HID, true><<<dim3(gM, 2), T>>>(nullptr, W2l, W2r);
    scatter_kernel<<<gScatter, T>>>(ei);
    combine_kernel<true><<<gZero, T>>>(b2, out);        // -> d_out
}

// round 12
// speedup vs baseline: 1.8256x; 1.8256x over previous
#include <cuda_runtime.h>
#include <cuda_bf16.h>
#include <cstdint>

#define N_NODES 100000
#define N_EDGES 200000
#define IN_DIM  384
#define HID     128

// ---------------- device scratch (no allocations allowed) ----------------
__device__ float g_PR [(size_t)N_NODES * 256];   // [P | R] per layer, reused
__device__ float g_h  [(size_t)N_NODES * HID];   // layer-1 output (fp32)
__device__ float g_agg[(size_t)N_NODES * HID];
__device__ int   g_cnt[N_NODES];
// Pre-split transposed weights: B[n][k] with n in [0,256) = [Wl | Wr] cols
__device__ __nv_bfloat16 g_B1h[256 * IN_DIM], g_B1l[256 * IN_DIM];
__device__ __nv_bfloat16 g_B2h[256 * HID],    g_B2l[256 * HID];

__device__ __forceinline__ int clampN(int v) {
    return v < 0 ? 0 : (v >= N_NODES ? N_NODES - 1 : v);
}
__device__ __forceinline__ uint32_t smem_u32(const void* p) {
    return (uint32_t)__cvta_generic_to_shared(p);
}
__device__ __forceinline__ uint32_t pack2(__nv_bfloat16 a, __nv_bfloat16 b) {
    return (uint32_t)__bfloat16_as_ushort(a) | ((uint32_t)__bfloat16_as_ushort(b) << 16);
}

// ---------------- family-safe tensor ops (sm_80+ PTX, no 'a' target) ----
__device__ __forceinline__ void ldsm4(uint32_t* r, uint32_t addr) {
    asm volatile("ldmatrix.sync.aligned.m8n8.x4.shared.b16 {%0,%1,%2,%3}, [%4];"
                 : "=r"(r[0]), "=r"(r[1]), "=r"(r[2]), "=r"(r[3]) : "r"(addr));
}
__device__ __forceinline__ void mma16816(float* c, const uint32_t* a,
                                         uint32_t b0, uint32_t b1) {
    asm volatile(
        "mma.sync.aligned.m16n8k16.row.col.f32.bf16.bf16.f32 "
        "{%0,%1,%2,%3}, {%4,%5,%6,%7}, {%8,%9}, {%0,%1,%2,%3};"
        : "+f"(c[0]), "+f"(c[1]), "+f"(c[2]), "+f"(c[3])
        : "r"(a[0]), "r"(a[1]), "r"(a[2]), "r"(a[3]), "r"(b0), "r"(b1));
}

// =====================================================================
// Split-bf16 HMMA GEMM: C[128-row tile, 128-col half] = A @ (Wl or Wr)
// grid = (782, 2); blockIdx.y picks Wl (cols 0-127) / Wr (cols 128-255).
// 8 warps: 4 along M (32 rows each) x 2 along N (64 cols each). BK=32.
// A fp32 -> (hi,lo) bf16 in the loader; 3 terms AhBh+AhBl+AlBh, fp32 acc.
// =====================================================================
#define SPAD 40   // bf16 row stride (32 data + 8 pad) -> conflict-free ldmatrix

template<int K, int LAYER>
__global__ __launch_bounds__(256, 2) void gemm_mma(const float* __restrict__ Aext)
{
    __shared__ __align__(16) __nv_bfloat16 Ah[128 * SPAD], Al[128 * SPAD];
    __shared__ __align__(16) __nv_bfloat16 Bh[128 * SPAD], Bl[128 * SPAD];

    const float* __restrict__ A = (LAYER == 1) ? Aext : g_h;
    const __nv_bfloat16* __restrict__ Bhg = (LAYER == 1) ? g_B1h : g_B2h;
    const __nv_bfloat16* __restrict__ Blg = (LAYER == 1) ? g_B1l : g_B2l;

    const int tid = threadIdx.x;
    const int wid = tid >> 5, lid = tid & 31;
    const int m0  = blockIdx.x * 128;
    const int by  = blockIdx.y;             // 0 = Wl half, 1 = Wr half
    const int r0  = (wid & 3) * 32;         // warp M offset
    const int n0  = (wid >> 2) * 64;        // warp N offset (local)

    const uint32_t sAh = smem_u32(Ah), sAl = smem_u32(Al);
    const uint32_t sBh = smem_u32(Bh), sBl = smem_u32(Bl);

    float acc[2][8][4];
#pragma unroll
    for (int s = 0; s < 2; s++)
#pragma unroll
        for (int t = 0; t < 8; t++)
#pragma unroll
            for (int q = 0; q < 4; q++) acc[s][t][q] = 0.f;

    // ldmatrix lane->row/col mapping (quad = lid>>3, l = lid&7)
    const int lq = lid >> 3, ll = lid & 7;
    // A frag quads: {rb+l,k0} {rb+8+l,k0} {rb+l,k0+8} {rb+8+l,k0+8}
    const int a_row_off = (lq & 1) * 8 + ll;
    const int a_col_off = (lq >> 1) * 8;
    // B frag quads: {nb+l,k0} {nb+l,k0+8} {nb+8+l,k0} {nb+8+l,k0+8}
    const int b_row_off = (lq >> 1) * 8 + ll;
    const int b_col_off = (lq & 1) * 8;

    for (int c = 0; c < K / 32; ++c) {
        const int c0 = c * 32;
        // ---- A tile: 128 rows x 32 fp32 -> hi/lo bf16 ----
#pragma unroll
        for (int i = 0; i < 4; ++i) {
            int idx = tid + i * 256;          // 0..1023
            int r   = idx >> 3, j4 = idx & 7;
            int gm  = m0 + r;
            float4 v = make_float4(0.f, 0.f, 0.f, 0.f);
            if (gm < N_NODES)
                v = *(const float4*)(A + (size_t)gm * K + c0 + j4 * 4);
            __nv_bfloat16 h0 = __float2bfloat16(v.x), h1 = __float2bfloat16(v.y);
            __nv_bfloat16 h2 = __float2bfloat16(v.z), h3 = __float2bfloat16(v.w);
            __nv_bfloat16 l0 = __float2bfloat16(v.x - __bfloat162float(h0));
            __nv_bfloat16 l1 = __float2bfloat16(v.y - __bfloat162float(h1));
            __nv_bfloat16 l2 = __float2bfloat16(v.z - __bfloat162float(h2));
            __nv_bfloat16 l3 = __float2bfloat16(v.w - __bfloat162float(h3));
            int o = r * SPAD + j4 * 4;
            *(uint2*)(Ah + o) = make_uint2(pack2(h0, h1), pack2(h2, h3));
            *(uint2*)(Al + o) = make_uint2(pack2(l0, l1), pack2(l2, l3));
        }
        // ---- B tile: 128 n-rows x 32 bf16 (pre-split, [n][k] layout) ----
#pragma unroll
        for (int i = 0; i < 2; ++i) {
            int idx = tid + i * 256;          // 0..511
            int n   = idx >> 2, j = idx & 3;
            size_t go = (size_t)(by * 128 + n) * K + c0 + j * 8;
            int o = n * SPAD + j * 8;
            *(uint4*)(Bh + o) = *(const uint4*)(Bhg + go);
            *(uint4*)(Bl + o) = *(const uint4*)(Blg + go);
        }
        __syncthreads();

        // ---- compute: 2 k-steps of 16 ----
#pragma unroll
        for (int ks = 0; ks < 2; ++ks) {
            const int k0 = ks * 16;
            uint32_t ah[2][4], al[2][4];
#pragma unroll
            for (int s = 0; s < 2; ++s) {
                uint32_t off = (uint32_t)((r0 + s * 16 + a_row_off) * SPAD
                                          + k0 + a_col_off) * 2;
                ldsm4(ah[s], sAh + off);
                ldsm4(al[s], sAl + off);
            }
#pragma unroll
            for (int g = 0; g < 4; ++g) {
                uint32_t bh4[4], bl4[4];
                uint32_t off = (uint32_t)((n0 + g * 16 + b_row_off) * SPAD
                                          + k0 + b_col_off) * 2;
                ldsm4(bh4, sBh + off);
                ldsm4(bl4, sBl + off);
#pragma unroll
                for (int h = 0; h < 2; ++h) {
                    int t = g * 2 + h;
#pragma unroll
                    for (int s = 0; s < 2; ++s) {
                        mma16816(acc[s][t], ah[s], bh4[h*2], bh4[h*2+1]);
                        mma16816(acc[s][t], ah[s], bl4[h*2], bl4[h*2+1]);
                        mma16816(acc[s][t], al[s], bh4[h*2], bh4[h*2+1]);
                    }
                }
            }
        }
        __syncthreads();
    }

    // ---- epilogue: acc -> g_PR (rows x 256), this CTA's 128-col half ----
#pragma unroll
    for (int s = 0; s < 2; ++s) {
        int row = m0 + r0 + s * 16 + (lid >> 2);
#pragma unroll
        for (int t = 0; t < 8; ++t) {
            int col = by * 128 + n0 + t * 8 + (lid & 3) * 2;
            if (row < N_NODES)
                *(float2*)(g_PR + (size_t)row * 256 + col) =
                    make_float2(acc[s][t][0], acc[s][t][1]);
            if (row + 8 < N_NODES)
                *(float2*)(g_PR + (size_t)(row + 8) * 256 + col) =
                    make_float2(acc[s][t][2], acc[s][t][3]);
        }
    }
}

// =====================================================================
// Weight split/transpose: B[n][k] = (n<128 ? Wl : Wr)[k][n&127], bf16 hi/lo
// =====================================================================
template<int K, int LAYER>
__global__ void split_w(const float* __restrict__ Wl, const float* __restrict__ Wr) {
    int idx = blockIdx.x * blockDim.x + threadIdx.x;
    if (idx >= 256 * K) return;
    int n = idx / K, k = idx - n * K;
    float v = (n < 128) ? Wl[(size_t)k * HID + n] : Wr[(size_t)k * HID + (n - 128)];
    __nv_bfloat16 h = __float2bfloat16(v);
    __nv_bfloat16 l = __float2bfloat16(v - __bfloat162float(h));
    if (LAYER == 1) { g_B1h[idx] = h; g_B1l[idx] = l; }
    else            { g_B2h[idx] = h; g_B2l[idx] = l; }
}

// =====================================================================
// Helper kernels (unchanged from passing R8 version)
// =====================================================================
__global__ void zero_kernel() {
    int idx = blockIdx.x * blockDim.x + threadIdx.x;
    if (idx < N_NODES * (HID / 4))
        ((float4*)g_agg)[idx] = make_float4(0.f, 0.f, 0.f, 0.f);
    if (idx < N_NODES) g_cnt[idx] = 0;
}

__global__ void count_kernel(const int* __restrict__ ei) {
    int e = blockIdx.x * blockDim.x + threadIdx.x;
    if (e < N_EDGES) atomicAdd(&g_cnt[clampN(ei[N_EDGES + e])], 1);
}

__global__ void scatter_kernel(const int* __restrict__ ei) {
    int idx = blockIdx.x * blockDim.x + threadIdx.x;
    if (idx >= N_EDGES * 32) return;
    int e = idx >> 5, q = idx & 31;
    int src = clampN(ei[e]);
    int dst = clampN(ei[N_EDGES + e]);
    float4 v = *(const float4*)(g_PR + (size_t)src * 256 + q * 4);
    float* d = g_agg + (size_t)dst * HID + q * 4;
    atomicAdd(d + 0, v.x);
    atomicAdd(d + 1, v.y);
    atomicAdd(d + 2, v.z);
    atomicAdd(d + 3, v.w);
}

template<bool L2>
__global__ void combine_kernel(const float* __restrict__ bias,
                               float* __restrict__ outp) {
    int idx = blockIdx.x * blockDim.x + threadIdx.x;
    if (idx >= N_NODES * 32) return;
    float* __restrict__ o = L2 ? outp : g_h;
    int n = idx >> 5, q = idx & 31;
    int c = g_cnt[n];
    float inv = 1.0f / (float)(c > 0 ? c : 1);
    float4 s  = ((const float4*)g_agg)[idx];
    float4 r  = *(const float4*)(g_PR + (size_t)n * 256 + 128 + q * 4);
    float4 bb = *(const float4*)(bias + q * 4);
    float4 v;
    v.x = fmaf(s.x, inv, bb.x + r.x);
    v.y = fmaf(s.y, inv, bb.y + r.y);
    v.z = fmaf(s.z, inv, bb.z + r.z);
    v.w = fmaf(s.w, inv, bb.w + r.w);
    if (!L2) {
        v.x = fmaxf(v.x, 0.f); v.y = fmaxf(v.y, 0.f);
        v.z = fmaxf(v.z, 0.f); v.w = fmaxf(v.w, 0.f);
        ((float4*)g_agg)[idx] = make_float4(0.f, 0.f, 0.f, 0.f);
    }
    ((float4*)o)[idx] = v;
}

// =====================================================================
extern "C" void kernel_launch(void* const* d_in, const int* in_sizes, int n_in,
                              void* d_out, int out_size) {
    const float* x   = (const float*)d_in[0];
    const int*   ei  = (const int*)d_in[1];      // int64 in ref -> int32 here
    const float* W1l = (const float*)d_in[2];
    const float* b1  = (const float*)d_in[3];
    const float* W1r = (const float*)d_in[4];
    const float* W2l = (const float*)d_in[5];
    const float* b2  = (const float*)d_in[6];
    const float* W2r = (const float*)d_in[7];
    float* out = (float*)d_out;

    const int T = 256;
    const int gM       = (N_NODES + 127) / 128;      // 782
    const int gZero    = (N_NODES * 32 + T - 1) / T;
    const int gCount   = (N_EDGES + T - 1) / T;
    const int gScatter = (N_EDGES * 32 + T - 1) / T;

    zero_kernel<<<gZero, T>>>();
    count_kernel<<<gCount, T>>>(ei);
    split_w<IN_DIM, 1><<<(256 * IN_DIM + T - 1) / T, T>>>(W1l, W1r);
    split_w<HID,    2><<<(256 * HID    + T - 1) / T, T>>>(W2l, W2r);

    // Layer 1: PR = x @ [W1l | W1r]
    gemm_mma<IN_DIM, 1><<<dim3(gM, 2), T>>>(x);
    scatter_kernel<<<gScatter, T>>>(ei);
    combine_kernel<false><<<gZero, T>>>(b1, nullptr);   // -> g_h (relu, agg reset)

    // Layer 2: PR = h @ [W2l | W2r]
    gemm_mma<HID, 2><<<dim3(gM, 2), T>>>(nullptr);
    scatter_kernel<<<gScatter, T>>>(ei);
    combine_kernel<true><<<gZero, T>>>(b2, out);        // -> d_out
}

// round 14
// speedup vs baseline: 2.0542x; 1.1252x over previous
#include <cuda_runtime.h>
#include <cuda_bf16.h>
#include <cstdint>

#define N_NODES 100000
#define N_EDGES 200000
#define IN_DIM  384
#define HID     128

// ---------------- device scratch (no allocations allowed) ----------------
__device__ float g_PR [(size_t)N_NODES * 256];   // [P | R] per layer, reused
__device__ float g_h  [(size_t)N_NODES * HID];   // layer-1 output (fp32)
__device__ float g_agg[(size_t)N_NODES * HID];
__device__ int   g_cnt[N_NODES];
// Pre-split transposed weights: B[n][k] with n in [0,256) = [Wl | Wr] cols
__device__ __nv_bfloat16 g_B1h[256 * IN_DIM], g_B1l[256 * IN_DIM];
__device__ __nv_bfloat16 g_B2h[256 * HID],    g_B2l[256 * HID];

__device__ __forceinline__ int clampN(int v) {
    return v < 0 ? 0 : (v >= N_NODES ? N_NODES - 1 : v);
}
__device__ __forceinline__ uint32_t smem_u32(const void* p) {
    return (uint32_t)__cvta_generic_to_shared(p);
}
__device__ __forceinline__ uint32_t pack2(__nv_bfloat16 a, __nv_bfloat16 b) {
    return (uint32_t)__bfloat16_as_ushort(a) | ((uint32_t)__bfloat16_as_ushort(b) << 16);
}

// ---------------- family-safe tensor ops (sm_80+ PTX, no 'a' target) ----
__device__ __forceinline__ void ldsm4(uint32_t* r, uint32_t addr) {
    asm volatile("ldmatrix.sync.aligned.m8n8.x4.shared.b16 {%0,%1,%2,%3}, [%4];"
                 : "=r"(r[0]), "=r"(r[1]), "=r"(r[2]), "=r"(r[3]) : "r"(addr));
}
__device__ __forceinline__ void mma16816(float* c, const uint32_t* a,
                                         uint32_t b0, uint32_t b1) {
    asm volatile(
        "mma.sync.aligned.m16n8k16.row.col.f32.bf16.bf16.f32 "
        "{%0,%1,%2,%3}, {%4,%5,%6,%7}, {%8,%9}, {%0,%1,%2,%3};"
        : "+f"(c[0]), "+f"(c[1]), "+f"(c[2]), "+f"(c[3])
        : "r"(a[0]), "r"(a[1]), "r"(a[2]), "r"(a[3]), "r"(b0), "r"(b1));
}

// =====================================================================
// Split-bf16 HMMA GEMM: C[128-row tile, 128-col half] = A @ (Wl or Wr)
// grid = (782, 2); blockIdx.y picks Wl (cols 0-127) / Wr (cols 128-255).
// 8 warps: 4 along M (32 rows each) x 2 along N (64 cols each). BK=32.
// A fp32 -> (hi,lo) bf16 in the loader; 3 terms AhBh+AhBl+AlBh, fp32 acc.
// =====================================================================
#define SPAD 40   // bf16 row stride (32 data + 8 pad) -> conflict-free ldmatrix

template<int K, int LAYER>
__global__ __launch_bounds__(256, 2) void gemm_mma(const float* __restrict__ Aext)
{
    __shared__ __align__(16) __nv_bfloat16 Ah[128 * SPAD], Al[128 * SPAD];
    __shared__ __align__(16) __nv_bfloat16 Bh[128 * SPAD], Bl[128 * SPAD];

    const float* __restrict__ A = (LAYER == 1) ? Aext : g_h;
    const __nv_bfloat16* __restrict__ Bhg = (LAYER == 1) ? g_B1h : g_B2h;
    const __nv_bfloat16* __restrict__ Blg = (LAYER == 1) ? g_B1l : g_B2l;

    const int tid = threadIdx.x;
    const int wid = tid >> 5, lid = tid & 31;
    const int m0  = blockIdx.x * 128;
    const int by  = blockIdx.y;             // 0 = Wl half, 1 = Wr half
    const int r0  = (wid & 3) * 32;         // warp M offset
    const int n0  = (wid >> 2) * 64;        // warp N offset (local)

    const uint32_t sAh = smem_u32(Ah), sAl = smem_u32(Al);
    const uint32_t sBh = smem_u32(Bh), sBl = smem_u32(Bl);

    float acc[2][8][4];
#pragma unroll
    for (int s = 0; s < 2; s++)
#pragma unroll
        for (int t = 0; t < 8; t++)
#pragma unroll
            for (int q = 0; q < 4; q++) acc[s][t][q] = 0.f;

    // ldmatrix lane->row/col mapping (quad = lid>>3, l = lid&7)
    const int lq = lid >> 3, ll = lid & 7;
    const int a_row_off = (lq & 1) * 8 + ll;
    const int a_col_off = (lq >> 1) * 8;
    const int b_row_off = (lq >> 1) * 8 + ll;
    const int b_col_off = (lq & 1) * 8;

    for (int c = 0; c < K / 32; ++c) {
        const int c0 = c * 32;
        // ---- A tile: 128 rows x 32 fp32 -> hi/lo bf16 ----
#pragma unroll
        for (int i = 0; i < 4; ++i) {
            int idx = tid + i * 256;          // 0..1023
            int r   = idx >> 3, j4 = idx & 7;
            int gm  = m0 + r;
            float4 v = make_float4(0.f, 0.f, 0.f, 0.f);
            if (gm < N_NODES)
                v = *(const float4*)(A + (size_t)gm * K + c0 + j4 * 4);
            __nv_bfloat16 h0 = __float2bfloat16(v.x), h1 = __float2bfloat16(v.y);
            __nv_bfloat16 h2 = __float2bfloat16(v.z), h3 = __float2bfloat16(v.w);
            __nv_bfloat16 l0 = __float2bfloat16(v.x - __bfloat162float(h0));
            __nv_bfloat16 l1 = __float2bfloat16(v.y - __bfloat162float(h1));
            __nv_bfloat16 l2 = __float2bfloat16(v.z - __bfloat162float(h2));
            __nv_bfloat16 l3 = __float2bfloat16(v.w - __bfloat162float(h3));
            int o = r * SPAD + j4 * 4;
            *(uint2*)(Ah + o) = make_uint2(pack2(h0, h1), pack2(h2, h3));
            *(uint2*)(Al + o) = make_uint2(pack2(l0, l1), pack2(l2, l3));
        }
        // ---- B tile: 128 n-rows x 32 bf16 (pre-split, [n][k] layout) ----
#pragma unroll
        for (int i = 0; i < 2; ++i) {
            int idx = tid + i * 256;          // 0..511
            int n   = idx >> 2, j = idx & 3;
            size_t go = (size_t)(by * 128 + n) * K + c0 + j * 8;
            int o = n * SPAD + j * 8;
            *(uint4*)(Bh + o) = *(const uint4*)(Bhg + go);
            *(uint4*)(Bl + o) = *(const uint4*)(Blg + go);
        }
        __syncthreads();

        // ---- compute: 2 k-steps of 16 ----
#pragma unroll
        for (int ks = 0; ks < 2; ++ks) {
            const int k0 = ks * 16;
            uint32_t ah[2][4], al[2][4];
#pragma unroll
            for (int s = 0; s < 2; ++s) {
                uint32_t off = (uint32_t)((r0 + s * 16 + a_row_off) * SPAD
                                          + k0 + a_col_off) * 2;
                ldsm4(ah[s], sAh + off);
                ldsm4(al[s], sAl + off);
            }
#pragma unroll
            for (int g = 0; g < 4; ++g) {
                uint32_t bh4[4], bl4[4];
                uint32_t off = (uint32_t)((n0 + g * 16 + b_row_off) * SPAD
                                          + k0 + b_col_off) * 2;
                ldsm4(bh4, sBh + off);
                ldsm4(bl4, sBl + off);
#pragma unroll
                for (int h = 0; h < 2; ++h) {
                    int t = g * 2 + h;
#pragma unroll
                    for (int s = 0; s < 2; ++s) {
                        mma16816(acc[s][t], ah[s], bh4[h*2], bh4[h*2+1]);
                        mma16816(acc[s][t], ah[s], bl4[h*2], bl4[h*2+1]);
                        mma16816(acc[s][t], al[s], bh4[h*2], bh4[h*2+1]);
                    }
                }
            }
        }
        __syncthreads();
    }

    // ---- epilogue: acc -> g_PR (rows x 256), this CTA's 128-col half ----
#pragma unroll
    for (int s = 0; s < 2; ++s) {
        int row = m0 + r0 + s * 16 + (lid >> 2);
#pragma unroll
        for (int t = 0; t < 8; ++t) {
            int col = by * 128 + n0 + t * 8 + (lid & 3) * 2;
            if (row < N_NODES)
                *(float2*)(g_PR + (size_t)row * 256 + col) =
                    make_float2(acc[s][t][0], acc[s][t][1]);
            if (row + 8 < N_NODES)
                *(float2*)(g_PR + (size_t)(row + 8) * 256 + col) =
                    make_float2(acc[s][t][2], acc[s][t][3]);
        }
    }
}

// =====================================================================
// Weight split/transpose, both layers in ONE launch (keeps gemm_mma as the
// 4th kernel launch -> it lands in ncu's profiled slot).
// idx < 256*IN_DIM: layer 1;  else: layer 2.
// =====================================================================
__global__ void split_w_all(const float* __restrict__ W1l, const float* __restrict__ W1r,
                            const float* __restrict__ W2l, const float* __restrict__ W2r) {
    int idx = blockIdx.x * blockDim.x + threadIdx.x;
    if (idx < 256 * IN_DIM) {
        int n = idx / IN_DIM, k = idx - n * IN_DIM;
        float v = (n < 128) ? W1l[(size_t)k * HID + n] : W1r[(size_t)k * HID + (n - 128)];
        __nv_bfloat16 h = __float2bfloat16(v);
        g_B1h[idx] = h;
        g_B1l[idx] = __float2bfloat16(v - __bfloat162float(h));
    } else if (idx < 256 * IN_DIM + 256 * HID) {
        int j = idx - 256 * IN_DIM;
        int n = j / HID, k = j - n * HID;
        float v = (n < 128) ? W2l[(size_t)k * HID + n] : W2r[(size_t)k * HID + (n - 128)];
        __nv_bfloat16 h = __float2bfloat16(v);
        g_B2h[j] = h;
        g_B2l[j] = __float2bfloat16(v - __bfloat162float(h));
    }
}

// =====================================================================
// Helper kernels
// =====================================================================
__global__ void zero_kernel() {
    int idx = blockIdx.x * blockDim.x + threadIdx.x;
    if (idx < N_NODES * (HID / 4))
        ((float4*)g_agg)[idx] = make_float4(0.f, 0.f, 0.f, 0.f);
    if (idx < N_NODES) g_cnt[idx] = 0;
}

__global__ void count_kernel(const int* __restrict__ ei) {
    int e = blockIdx.x * blockDim.x + threadIdx.x;
    if (e < N_EDGES) atomicAdd(&g_cnt[clampN(ei[N_EDGES + e])], 1);
}

// agg[dst] += P[src] via vectorized red.global.add.v4.f32 (PTX 8.1+, sm_90+)
__global__ void scatter_kernel(const int* __restrict__ ei) {
    int idx = blockIdx.x * blockDim.x + threadIdx.x;
    if (idx >= N_EDGES * 32) return;
    int e = idx >> 5, q = idx & 31;
    int src = clampN(ei[e]);
    int dst = clampN(ei[N_EDGES + e]);
    float4 v = *(const float4*)(g_PR + (size_t)src * 256 + q * 4);
    float* d = g_agg + (size_t)dst * HID + q * 4;
    asm volatile("red.global.add.v4.f32 [%0], {%1, %2, %3, %4};"
                 :: "l"(d), "f"(v.x), "f"(v.y), "f"(v.z), "f"(v.w) : "memory");
}

template<bool L2>
__global__ void combine_kernel(const float* __restrict__ bias,
                               float* __restrict__ outp) {
    int idx = blockIdx.x * blockDim.x + threadIdx.x;
    if (idx >= N_NODES * 32) return;
    float* __restrict__ o = L2 ? outp : g_h;
    int n = idx >> 5, q = idx & 31;
    int c = g_cnt[n];
    float inv = 1.0f / (float)(c > 0 ? c : 1);
    float4 s  = ((const float4*)g_agg)[idx];
    float4 r  = *(const float4*)(g_PR + (size_t)n * 256 + 128 + q * 4);
    float4 bb = *(const float4*)(bias + q * 4);
    float4 v;
    v.x = fmaf(s.x, inv, bb.x + r.x);
    v.y = fmaf(s.y, inv, bb.y + r.y);
    v.z = fmaf(s.z, inv, bb.z + r.z);
    v.w = fmaf(s.w, inv, bb.w + r.w);
    if (!L2) {
        v.x = fmaxf(v.x, 0.f); v.y = fmaxf(v.y, 0.f);
        v.z = fmaxf(v.z, 0.f); v.w = fmaxf(v.w, 0.f);
        ((float4*)g_agg)[idx] = make_float4(0.f, 0.f, 0.f, 0.f);
    }
    ((float4*)o)[idx] = v;
}

// =====================================================================
extern "C" void kernel_launch(void* const* d_in, const int* in_sizes, int n_in,
                              void* d_out, int out_size) {
    const float* x   = (const float*)d_in[0];
    const int*   ei  = (const int*)d_in[1];      // int64 in ref -> int32 here
    const float* W1l = (const float*)d_in[2];
    const float* b1  = (const float*)d_in[3];
    const float* W1r = (const float*)d_in[4];
    const float* W2l = (const float*)d_in[5];
    const float* b2  = (const float*)d_in[6];
    const float* W2r = (const float*)d_in[7];
    float* out = (float*)d_out;

    const int T = 256;
    const int gM       = (N_NODES + 127) / 128;      // 782
    const int gZero    = (N_NODES * 32 + T - 1) / T;
    const int gCount   = (N_EDGES + T - 1) / T;
    const int gScatter = (N_EDGES * 32 + T - 1) / T;
    const int nSplit   = 256 * IN_DIM + 256 * HID;

    zero_kernel<<<gZero, T>>>();                               // 1
    count_kernel<<<gCount, T>>>(ei);                           // 2
    split_w_all<<<(nSplit + T - 1) / T, T>>>(W1l, W1r, W2l, W2r); // 3

    // Layer 1: PR = x @ [W1l | W1r]
    gemm_mma<IN_DIM, 1><<<dim3(gM, 2), T>>>(x);                // 4 <- profiled slot
    scatter_kernel<<<gScatter, T>>>(ei);                       // 5
    combine_kernel<false><<<gZero, T>>>(b1, nullptr);          // 6 -> g_h

    // Layer 2: PR = h @ [W2l | W2r]
    gemm_mma<HID, 2><<<dim3(gM, 2), T>>>(nullptr);             // 7
    scatter_kernel<<<gScatter, T>>>(ei);                       // 8
    combine_kernel<true><<<gZero, T>>>(b2, out);               // 9 -> d_out
}

// round 16
// speedup vs baseline: 2.2376x; 1.0893x over previous
#include <cuda_runtime.h>
#include <cuda_bf16.h>
#include <cstdint>

#define N_NODES 100000
#define N_EDGES 200000
#define IN_DIM  384
#define HID     128

// ---------------- device scratch (no allocations allowed) ----------------
__device__ float g_PR [(size_t)N_NODES * 256];   // [P | R] per layer, reused
__device__ float g_h  [(size_t)N_NODES * HID];   // layer-1 output (fp32)
__device__ float g_agg[(size_t)N_NODES * HID];
__device__ int   g_cnt[N_NODES];
// Pre-split transposed weights: B[n][k] with n in [0,256) = [Wl | Wr] cols
__device__ __nv_bfloat16 g_B1h[256 * IN_DIM], g_B1l[256 * IN_DIM];
__device__ __nv_bfloat16 g_B2h[256 * HID],    g_B2l[256 * HID];

__device__ __forceinline__ int clampN(int v) {
    return v < 0 ? 0 : (v >= N_NODES ? N_NODES - 1 : v);
}
__device__ __forceinline__ uint32_t smem_u32(const void* p) {
    return (uint32_t)__cvta_generic_to_shared(p);
}
__device__ __forceinline__ uint32_t pack2(__nv_bfloat16 a, __nv_bfloat16 b) {
    return (uint32_t)__bfloat16_as_ushort(a) | ((uint32_t)__bfloat16_as_ushort(b) << 16);
}

// ---------------- family-safe tensor / async ops (sm_80+ PTX) ----------
__device__ __forceinline__ void ldsm4(uint32_t* r, uint32_t addr) {
    asm volatile("ldmatrix.sync.aligned.m8n8.x4.shared.b16 {%0,%1,%2,%3}, [%4];"
                 : "=r"(r[0]), "=r"(r[1]), "=r"(r[2]), "=r"(r[3]) : "r"(addr));
}
__device__ __forceinline__ void mma16816(float* c, const uint32_t* a,
                                         uint32_t b0, uint32_t b1) {
    asm volatile(
        "mma.sync.aligned.m16n8k16.row.col.f32.bf16.bf16.f32 "
        "{%0,%1,%2,%3}, {%4,%5,%6,%7}, {%8,%9}, {%0,%1,%2,%3};"
        : "+f"(c[0]), "+f"(c[1]), "+f"(c[2]), "+f"(c[3])
        : "r"(a[0]), "r"(a[1]), "r"(a[2]), "r"(a[3]), "r"(b0), "r"(b1));
}
__device__ __forceinline__ void cpasync16(uint32_t s, const void* g) {
    asm volatile("cp.async.cg.shared.global [%0], [%1], 16;" :: "r"(s), "l"(g));
}
__device__ __forceinline__ void cpcommit() {
    asm volatile("cp.async.commit_group;" ::: "memory");
}
template<int N> __device__ __forceinline__ void cpwait() {
    asm volatile("cp.async.wait_group %0;" :: "n"(N) : "memory");
}

// =====================================================================
// Split-bf16 HMMA GEMM, software-pipelined:
//   B: cp.async 2-stage double buffer (bf16 pre-split in global)
//   A: register prefetch (LDG next chunk before compute, convert+STS after)
// C[128-row tile, 128-col half] = A @ (Wl or Wr); grid (782, 2).
// 8 warps: 4 along M x 2 along N; BK=32; AhBh+AhBl+AlBh, fp32 acc.
// =====================================================================
#define SPAD 40   // bf16 row stride (32 data + 8 pad) -> conflict-free ldmatrix
#define GEMM_DSMEM (30720 * 2)   // 6 tiles of 128*SPAD bf16 = 61440 B

template<int K, int LAYER>
__global__ __launch_bounds__(256, 2) void gemm_mma(const float* __restrict__ Aext)
{
    extern __shared__ __align__(16) __nv_bfloat16 dsm[];
    __nv_bfloat16* const Ah  = dsm;
    __nv_bfloat16* const Al  = dsm + 5120;
    __nv_bfloat16* const Bh0 = dsm + 10240;
    __nv_bfloat16* const Bl0 = dsm + 15360;
    __nv_bfloat16* const Bh1 = dsm + 20480;
    __nv_bfloat16* const Bl1 = dsm + 25600;

    const float* __restrict__ A = (LAYER == 1) ? Aext : g_h;
    const __nv_bfloat16* __restrict__ Bhg = (LAYER == 1) ? g_B1h : g_B2h;
    const __nv_bfloat16* __restrict__ Blg = (LAYER == 1) ? g_B1l : g_B2l;

    const int tid = threadIdx.x;
    const int wid = tid >> 5, lid = tid & 31;
    const int m0  = blockIdx.x * 128;
    const int by  = blockIdx.y;             // 0 = Wl half, 1 = Wr half
    const int r0  = (wid & 3) * 32;         // warp M offset
    const int n0  = (wid >> 2) * 64;        // warp N offset (local)

    const uint32_t sAh = smem_u32(Ah), sAl = smem_u32(Al);

    float acc[2][8][4];
#pragma unroll
    for (int s = 0; s < 2; s++)
#pragma unroll
        for (int t = 0; t < 8; t++)
#pragma unroll
            for (int q = 0; q < 4; q++) acc[s][t][q] = 0.f;

    // ldmatrix lane->row/col mapping
    const int lq = lid >> 3, ll = lid & 7;
    const int a_row_off = (lq & 1) * 8 + ll;
    const int a_col_off = (lq >> 1) * 8;
    const int b_row_off = (lq >> 1) * 8 + ll;
    const int b_col_off = (lq & 1) * 8;

    // per-thread A mapping: 4 float4 tiles (idx = tid + i*256)
    const int ar = tid >> 3;            // row for i=0 block base (idx>>3)
    const int aj = tid & 7;             // float4 col
    // per-thread B cp.async mapping: 2 chunks per matrix (idx = tid + i*256)
    // n = idx>>2, j = idx&3

    float4 areg[4];
    const int CH = K / 32;

    // ---------------- prologue: A(0) LDG, B(0) cp.async, A(0) STS --------
#pragma unroll
    for (int i = 0; i < 4; ++i) {
        int idx = tid + i * 256;
        int r = idx >> 3, j4 = idx & 7;
        int gm = m0 + r;
        areg[i] = (gm < N_NODES) ? *(const float4*)(A + (size_t)gm * K + j4 * 4)
                                 : make_float4(0.f, 0.f, 0.f, 0.f);
    }
    {
        const uint32_t sbh = smem_u32(Bh0), sbl = smem_u32(Bl0);
#pragma unroll
        for (int i = 0; i < 2; ++i) {
            int idx = tid + i * 256;
            int n = idx >> 2, j = idx & 3;
            size_t go = (size_t)(by * 128 + n) * K + j * 8;
            uint32_t so = (uint32_t)(n * SPAD + j * 8) * 2;
            cpasync16(sbh + so, Bhg + go);
            cpasync16(sbl + so, Blg + go);
        }
        cpcommit();
    }
#pragma unroll
    for (int i = 0; i < 4; ++i) {
        int idx = tid + i * 256;
        int r = idx >> 3, j4 = idx & 7;
        float4 v = areg[i];
        __nv_bfloat16 h0 = __float2bfloat16(v.x), h1 = __float2bfloat16(v.y);
        __nv_bfloat16 h2 = __float2bfloat16(v.z), h3 = __float2bfloat16(v.w);
        __nv_bfloat16 l0 = __float2bfloat16(v.x - __bfloat162float(h0));
        __nv_bfloat16 l1 = __float2bfloat16(v.y - __bfloat162float(h1));
        __nv_bfloat16 l2 = __float2bfloat16(v.z - __bfloat162float(h2));
        __nv_bfloat16 l3 = __float2bfloat16(v.w - __bfloat162float(h3));
        int o = r * SPAD + j4 * 4;
        *(uint2*)(Ah + o) = make_uint2(pack2(h0, h1), pack2(h2, h3));
        *(uint2*)(Al + o) = make_uint2(pack2(l0, l1), pack2(l2, l3));
    }

    // ---------------- main loop ----------------
    for (int c = 0; c < CH; ++c) {
        if (c + 1 < CH) {
            const int c1 = (c + 1) * 32;
            // A(c+1) -> regs (latency hidden behind compute below)
#pragma unroll
            for (int i = 0; i < 4; ++i) {
                int idx = tid + i * 256;
                int r = idx >> 3, j4 = idx & 7;
                int gm = m0 + r;
                areg[i] = (gm < N_NODES)
                        ? *(const float4*)(A + (size_t)gm * K + c1 + j4 * 4)
                        : make_float4(0.f, 0.f, 0.f, 0.f);
            }
            // B(c+1) -> other stage
            const uint32_t sbh = smem_u32(((c + 1) & 1) ? Bh1 : Bh0);
            const uint32_t sbl = smem_u32(((c + 1) & 1) ? Bl1 : Bl0);
#pragma unroll
            for (int i = 0; i < 2; ++i) {
                int idx = tid + i * 256;
                int n = idx >> 2, j = idx & 3;
                size_t go = (size_t)(by * 128 + n) * K + c1 + j * 8;
                uint32_t so = (uint32_t)(n * SPAD + j * 8) * 2;
                cpasync16(sbh + so, Bhg + go);
                cpasync16(sbl + so, Blg + go);
            }
            cpcommit();
            cpwait<1>();   // B(c) complete (newest group may be in flight)
        } else {
            cpwait<0>();
        }
        __syncthreads();   // A(c) STS + B(c) visible to all warps

        // ---- compute chunk c ----
        const uint32_t sBh = smem_u32((c & 1) ? Bh1 : Bh0);
        const uint32_t sBl = smem_u32((c & 1) ? Bl1 : Bl0);
#pragma unroll
        for (int ks = 0; ks < 2; ++ks) {
            const int k0 = ks * 16;
            uint32_t ah[2][4], al[2][4];
#pragma unroll
            for (int s = 0; s < 2; ++s) {
                uint32_t off = (uint32_t)((r0 + s * 16 + a_row_off) * SPAD
                                          + k0 + a_col_off) * 2;
                ldsm4(ah[s], sAh + off);
                ldsm4(al[s], sAl + off);
            }
#pragma unroll
            for (int g = 0; g < 4; ++g) {
                uint32_t bh4[4], bl4[4];
                uint32_t off = (uint32_t)((n0 + g * 16 + b_row_off) * SPAD
                                          + k0 + b_col_off) * 2;
                ldsm4(bh4, sBh + off);
                ldsm4(bl4, sBl + off);
#pragma unroll
                for (int h = 0; h < 2; ++h) {
                    int t = g * 2 + h;
#pragma unroll
                    for (int s = 0; s < 2; ++s) {
                        mma16816(acc[s][t], ah[s], bh4[h*2], bh4[h*2+1]);
                        mma16816(acc[s][t], ah[s], bl4[h*2], bl4[h*2+1]);
                        mma16816(acc[s][t], al[s], bh4[h*2], bh4[h*2+1]);
                    }
                }
            }
        }
        __syncthreads();   // everyone done reading Ah/Al before overwrite

        if (c + 1 < CH) {
            // convert+store A(c+1) into the (single) A buffer
#pragma unroll
            for (int i = 0; i < 4; ++i) {
                int idx = tid + i * 256;
                int r = idx >> 3, j4 = idx & 7;
                float4 v = areg[i];
                __nv_bfloat16 h0 = __float2bfloat16(v.x), h1 = __float2bfloat16(v.y);
                __nv_bfloat16 h2 = __float2bfloat16(v.z), h3 = __float2bfloat16(v.w);
                __nv_bfloat16 l0 = __float2bfloat16(v.x - __bfloat162float(h0));
                __nv_bfloat16 l1 = __float2bfloat16(v.y - __bfloat162float(h1));
                __nv_bfloat16 l2 = __float2bfloat16(v.z - __bfloat162float(h2));
                __nv_bfloat16 l3 = __float2bfloat16(v.w - __bfloat162float(h3));
                int o = r * SPAD + j4 * 4;
                *(uint2*)(Ah + o) = make_uint2(pack2(h0, h1), pack2(h2, h3));
                *(uint2*)(Al + o) = make_uint2(pack2(l0, l1), pack2(l2, l3));
            }
        }
    }

    // ---- epilogue: acc -> g_PR (rows x 256), this CTA's 128-col half ----
#pragma unroll
    for (int s = 0; s < 2; ++s) {
        int row = m0 + r0 + s * 16 + (lid >> 2);
#pragma unroll
        for (int t = 0; t < 8; ++t) {
            int col = by * 128 + n0 + t * 8 + (lid & 3) * 2;
            if (row < N_NODES)
                *(float2*)(g_PR + (size_t)row * 256 + col) =
                    make_float2(acc[s][t][0], acc[s][t][1]);
            if (row + 8 < N_NODES)
                *(float2*)(g_PR + (size_t)(row + 8) * 256 + col) =
                    make_float2(acc[s][t][2], acc[s][t][3]);
        }
    }
}

// =====================================================================
// Weight split/transpose, both layers in one launch (keeps gemm_mma 4th).
// =====================================================================
__global__ void split_w_all(const float* __restrict__ W1l, const float* __restrict__ W1r,
                            const float* __restrict__ W2l, const float* __restrict__ W2r) {
    int idx = blockIdx.x * blockDim.x + threadIdx.x;
    if (idx < 256 * IN_DIM) {
        int n = idx / IN_DIM, k = idx - n * IN_DIM;
        float v = (n < 128) ? W1l[(size_t)k * HID + n] : W1r[(size_t)k * HID + (n - 128)];
        __nv_bfloat16 h = __float2bfloat16(v);
        g_B1h[idx] = h;
        g_B1l[idx] = __float2bfloat16(v - __bfloat162float(h));
    } else if (idx < 256 * IN_DIM + 256 * HID) {
        int j = idx - 256 * IN_DIM;
        int n = j / HID, k = j - n * HID;
        float v = (n < 128) ? W2l[(size_t)k * HID + n] : W2r[(size_t)k * HID + (n - 128)];
        __nv_bfloat16 h = __float2bfloat16(v);
        g_B2h[j] = h;
        g_B2l[j] = __float2bfloat16(v - __bfloat162float(h));
    }
}

// =====================================================================
// Helper kernels
// =====================================================================
__global__ void zero_kernel() {
    int idx = blockIdx.x * blockDim.x + threadIdx.x;
    if (idx < N_NODES * (HID / 4))
        ((float4*)g_agg)[idx] = make_float4(0.f, 0.f, 0.f, 0.f);
    if (idx < N_NODES) g_cnt[idx] = 0;
}

__global__ void count_kernel(const int* __restrict__ ei) {
    int e = blockIdx.x * blockDim.x + threadIdx.x;
    if (e < N_EDGES) atomicAdd(&g_cnt[clampN(ei[N_EDGES + e])], 1);
}

// agg[dst] += P[src] via vectorized red.global.add.v4.f32 (PTX 8.1+, sm_90+)
__global__ void scatter_kernel(const int* __restrict__ ei) {
    int idx = blockIdx.x * blockDim.x + threadIdx.x;
    if (idx >= N_EDGES * 32) return;
    int e = idx >> 5, q = idx & 31;
    int src = clampN(ei[e]);
    int dst = clampN(ei[N_EDGES + e]);
    float4 v = *(const float4*)(g_PR + (size_t)src * 256 + q * 4);
    float* d = g_agg + (size_t)dst * HID + q * 4;
    asm volatile("red.global.add.v4.f32 [%0], {%1, %2, %3, %4};"
                 :: "l"(d), "f"(v.x), "f"(v.y), "f"(v.z), "f"(v.w) : "memory");
}

template<bool L2>
__global__ void combine_kernel(const float* __restrict__ bias,
                               float* __restrict__ outp) {
    int idx = blockIdx.x * blockDim.x + threadIdx.x;
    if (idx >= N_NODES * 32) return;
    float* __restrict__ o = L2 ? outp : g_h;
    int n = idx >> 5, q = idx & 31;
    int c = g_cnt[n];
    float inv = 1.0f / (float)(c > 0 ? c : 1);
    float4 s  = ((const float4*)g_agg)[idx];
    float4 r  = *(const float4*)(g_PR + (size_t)n * 256 + 128 + q * 4);
    float4 bb = *(const float4*)(bias + q * 4);
    float4 v;
    v.x = fmaf(s.x, inv, bb.x + r.x);
    v.y = fmaf(s.y, inv, bb.y + r.y);
    v.z = fmaf(s.z, inv, bb.z + r.z);
    v.w = fmaf(s.w, inv, bb.w + r.w);
    if (!L2) {
        v.x = fmaxf(v.x, 0.f); v.y = fmaxf(v.y, 0.f);
        v.z = fmaxf(v.z, 0.f); v.w = fmaxf(v.w, 0.f);
        ((float4*)g_agg)[idx] = make_float4(0.f, 0.f, 0.f, 0.f);
    }
    ((float4*)o)[idx] = v;
}

// =====================================================================
extern "C" void kernel_launch(void* const* d_in, const int* in_sizes, int n_in,
                              void* d_out, int out_size) {
    const float* x   = (const float*)d_in[0];
    const int*   ei  = (const int*)d_in[1];      // int64 in ref -> int32 here
    const float* W1l = (const float*)d_in[2];
    const float* b1  = (const float*)d_in[3];
    const float* W1r = (const float*)d_in[4];
    const float* W2l = (const float*)d_in[5];
    const float* b2  = (const float*)d_in[6];
    const float* W2r = (const float*)d_in[7];
    float* out = (float*)d_out;

    // unconditional (no static guards): host-side only, not captured as graph
    // nodes; zero cost during graph replay.
    cudaFuncSetAttribute(gemm_mma<IN_DIM, 1>,
                         cudaFuncAttributeMaxDynamicSharedMemorySize, GEMM_DSMEM);
    cudaFuncSetAttribute(gemm_mma<HID, 2>,
                         cudaFuncAttributeMaxDynamicSharedMemorySize, GEMM_DSMEM);

    const int T = 256;
    const int gM       = (N_NODES + 127) / 128;      // 782
    const int gZero    = (N_NODES * 32 + T - 1) / T;
    const int gCount   = (N_EDGES + T - 1) / T;
    const int gScatter = (N_EDGES * 32 + T - 1) / T;
    const int nSplit   = 256 * IN_DIM + 256 * HID;

    zero_kernel<<<gZero, T>>>();                                  // 1
    count_kernel<<<gCount, T>>>(ei);                              // 2
    split_w_all<<<(nSplit + T - 1) / T, T>>>(W1l, W1r, W2l, W2r); // 3

    // Layer 1: PR = x @ [W1l | W1r]
    gemm_mma<IN_DIM, 1><<<dim3(gM, 2), T, GEMM_DSMEM>>>(x);       // 4 <- profiled
    scatter_kernel<<<gScatter, T>>>(ei);                          // 5
    combine_kernel<false><<<gZero, T>>>(b1, nullptr);             // 6 -> g_h

    // Layer 2: PR = h @ [W2l | W2r]
    gemm_mma<HID, 2><<<dim3(gM, 2), T, GEMM_DSMEM>>>(nullptr);    // 7
    scatter_kernel<<<gScatter, T>>>(ei);                          // 8
    combine_kernel<true><<<gZero, T>>>(b2, out);                  // 9 -> d_out
}